// round 15
// baseline (speedup 1.0000x reference)
#include <cuda_runtime.h>
#include <cuda_fp16.h>
#include <cstdint>

#define N_NODES 4096
#define MAXH 4

// ---------------- scratch (static device globals; no allocation) ----------------
__device__ unsigned g_maskw[N_NODES * 128];            // 2 MB adjacency bitmask
__device__ __half   g_h16T [MAXH * 64 * N_NODES];      // per-head features fp16, transposed [h][o][n]
__device__ float    g_el[MAXH * N_NODES], g_er[MAXH * N_NODES];
__device__ unsigned g_Cbits[MAXH];                     // per-head max(er), order-preserving uint
__device__ __half   g_x16 [N_NODES * 128];             // layer-0 input, fp16
__device__ __half   g_bufA[N_NODES * 256];             // layer-0 output, fp16
__device__ __half   g_bufB[N_NODES * 256];             // layer-1 output, fp16
__device__ float    g_part[16 * N_NODES * 68];         // split-m partials (SPLIT*H <= 16 slabs)

// order-preserving float <-> uint mapping (exact max via atomicMax)
__device__ __forceinline__ unsigned fmap(float x) {
    unsigned b = __float_as_uint(x);
    return (b & 0x80000000u) ? ~b : (b | 0x80000000u);
}
__device__ __forceinline__ float funmap(unsigned m) {
    return __uint_as_float((m & 0x80000000u) ? (m & 0x7FFFFFFFu) : ~m);
}

// ---------------- adjacency -> bitmask ----------------
__global__ void k_mask(const int* __restrict__ adj, unsigned* __restrict__ maskw) {
    int n = blockIdx.x;
    int tid = threadIdx.x;
    const int* row = adj + (size_t)n * N_NODES;
#pragma unroll
    for (int it = 0; it < 4; it++) {
        int m = it * 1024 + tid;
        unsigned b = __ballot_sync(0xffffffffu, row[m] > 0);
        if ((tid & 31) == 0) maskw[n * 128 + (m >> 5)] = b;
    }
}

// ---------------- x fp32 -> fp16 (+ reset g_Cbits for layer 0) ----------------
__global__ void k_x2h(const float* __restrict__ in, __half* __restrict__ out, int n4) {
    if (blockIdx.x == 0 && threadIdx.x < MAXH) g_Cbits[threadIdx.x] = 0u;
    int i = blockIdx.x * 256 + threadIdx.x;
    if (i < n4) {
        float4 f = reinterpret_cast<const float4*>(in)[i];
        __half2 lo = __floats2half2_rn(f.x, f.y);
        __half2 hi = __floats2half2_rn(f.z, f.w);
        reinterpret_cast<uint2*>(out)[i] =
            make_uint2(*reinterpret_cast<unsigned*>(&lo), *reinterpret_cast<unsigned*>(&hi));
    }
}

__device__ __forceinline__ unsigned smem_u32(const void* p) {
    return (unsigned)__cvta_generic_to_shared(p);
}
__device__ __forceinline__ __half2 u2h(unsigned u) { return *reinterpret_cast<__half2*>(&u); }
__device__ __forceinline__ unsigned h2u(__half2 h) { return *reinterpret_cast<unsigned*>(&h); }

// ---------------- tensor-core feature GEMM + fused e_l/e_r + max(er) ----------------
template<int K>
__global__ void __launch_bounds__(256) k_feat_tc(
    const __half* __restrict__ in16, const float* __restrict__ W,
    const float* __restrict__ a,
    __half* __restrict__ h16T, float* __restrict__ el, float* __restrict__ er) {
    __shared__ __half As[128 * 72];    // [row][k] padded
    __shared__ __half WT[64 * 72];     // [o][k]  padded
    __shared__ float smax[8];
    const int h  = blockIdx.y;
    const int nb = blockIdx.x * 128;
    const int tid = threadIdx.x;
    const int lane = tid & 31, warp = tid >> 5;
    const int tig = lane & 3, gid = lane >> 2;
    const float* Wh = W + (size_t)h * K * 64;

    float acc[8][4];
#pragma unroll
    for (int i = 0; i < 8; i++)
#pragma unroll
        for (int j = 0; j < 4; j++) acc[i][j] = 0.f;

    const int arow = warp * 16 + (lane & 15);
    const unsigned aaddr = smem_u32(&As[arow * 72 + (lane >> 4) * 8]);

#pragma unroll 1
    for (int k0 = 0; k0 < K; k0 += 64) {
        __syncthreads();
#pragma unroll
        for (int i = 0; i < 4; i++) {
            int idx = tid + i * 256;       // 0..1023
            int r = idx >> 3, c = idx & 7;
            *reinterpret_cast<uint4*>(&As[r * 72 + c * 8]) =
                *reinterpret_cast<const uint4*>(in16 + (size_t)(nb + r) * K + k0 + c * 8);
        }
#pragma unroll
        for (int i = 0; i < 4; i++) {
            int idx = tid + i * 256;
            int kk = idx >> 4, og = (idx & 15) * 4;
            float4 w4 = *reinterpret_cast<const float4*>(&Wh[(size_t)(k0 + kk) * 64 + og]);
            WT[(og + 0) * 72 + kk] = __float2half_rn(w4.x);
            WT[(og + 1) * 72 + kk] = __float2half_rn(w4.y);
            WT[(og + 2) * 72 + kk] = __float2half_rn(w4.z);
            WT[(og + 3) * 72 + kk] = __float2half_rn(w4.w);
        }
        __syncthreads();
#pragma unroll
        for (int kc = 0; kc < 4; kc++) {
            unsigned a0, a1, a2, a3;
            asm volatile("ldmatrix.sync.aligned.m8n8.x4.shared.b16 {%0,%1,%2,%3}, [%4];\n"
                         : "=r"(a0), "=r"(a1), "=r"(a2), "=r"(a3)
                         : "r"(aaddr + kc * 32));
#pragma unroll
            for (int ncp = 0; ncp < 4; ncp++) {
                int g = lane >> 3, r = lane & 7;
                int brw  = ncp * 16 + (g >> 1) * 8 + r;
                int bcol = kc * 16 + (g & 1) * 8;
                unsigned baddr = smem_u32(&WT[brw * 72 + bcol]);
                unsigned b0, b1, b2, b3;
                asm volatile("ldmatrix.sync.aligned.m8n8.x4.shared.b16 {%0,%1,%2,%3}, [%4];\n"
                             : "=r"(b0), "=r"(b1), "=r"(b2), "=r"(b3) : "r"(baddr));
                asm volatile(
                    "mma.sync.aligned.m16n8k16.row.col.f32.f16.f16.f32 "
                    "{%0,%1,%2,%3}, {%4,%5,%6,%7}, {%8,%9}, {%0,%1,%2,%3};\n"
                    : "+f"(acc[2 * ncp][0]), "+f"(acc[2 * ncp][1]),
                      "+f"(acc[2 * ncp][2]), "+f"(acc[2 * ncp][3])
                    : "r"(a0), "r"(a1), "r"(a2), "r"(a3), "r"(b0), "r"(b1));
                asm volatile(
                    "mma.sync.aligned.m16n8k16.row.col.f32.f16.f16.f32 "
                    "{%0,%1,%2,%3}, {%4,%5,%6,%7}, {%8,%9}, {%0,%1,%2,%3};\n"
                    : "+f"(acc[2 * ncp + 1][0]), "+f"(acc[2 * ncp + 1][1]),
                      "+f"(acc[2 * ncp + 1][2]), "+f"(acc[2 * ncp + 1][3])
                    : "r"(a0), "r"(a1), "r"(a2), "r"(a3), "r"(b2), "r"(b3));
            }
        }
    }

    // ---- epilogue: h16T stores + el/er + CTA max(er) -> atomicMax ----
    const int n_lo = nb + warp * 16 + gid;
    const int n_hi = n_lo + 8;
    const int hb = h * N_NODES;
    __half* hTb = h16T + ((size_t)h * 64) * N_NODES;
    const float* ah = a + h * 128;

    float pl0 = 0.f, pl1 = 0.f, pr0 = 0.f, pr1 = 0.f;
#pragma unroll
    for (int nc = 0; nc < 8; nc++) {
        const int c0 = nc * 8 + 2 * tig;
        hTb[(size_t)c0 * N_NODES + n_lo]       = __float2half_rn(acc[nc][0]);
        hTb[(size_t)(c0 + 1) * N_NODES + n_lo] = __float2half_rn(acc[nc][1]);
        hTb[(size_t)c0 * N_NODES + n_hi]       = __float2half_rn(acc[nc][2]);
        hTb[(size_t)(c0 + 1) * N_NODES + n_hi] = __float2half_rn(acc[nc][3]);
        const float al0 = ah[c0], al1 = ah[c0 + 1];
        const float ar0 = ah[64 + c0], ar1 = ah[64 + c0 + 1];
        pl0 = fmaf(acc[nc][0], al0, fmaf(acc[nc][1], al1, pl0));
        pl1 = fmaf(acc[nc][2], al0, fmaf(acc[nc][3], al1, pl1));
        pr0 = fmaf(acc[nc][0], ar0, fmaf(acc[nc][1], ar1, pr0));
        pr1 = fmaf(acc[nc][2], ar0, fmaf(acc[nc][3], ar1, pr1));
    }
#pragma unroll
    for (int o = 1; o < 4; o <<= 1) {
        pl0 += __shfl_xor_sync(0xffffffffu, pl0, o);
        pl1 += __shfl_xor_sync(0xffffffffu, pl1, o);
        pr0 += __shfl_xor_sync(0xffffffffu, pr0, o);
        pr1 += __shfl_xor_sync(0xffffffffu, pr1, o);
    }
    if (tig == 0) {
        el[hb + n_lo] = pl0; el[hb + n_hi] = pl1;
        er[hb + n_lo] = pr0; er[hb + n_hi] = pr1;
    }
    // warp max of er (pr values valid in all lanes of each 4-lane group)
    float mx = fmaxf(pr0, pr1);
#pragma unroll
    for (int o = 4; o < 32; o <<= 1) mx = fmaxf(mx, __shfl_xor_sync(0xffffffffu, mx, o));
    if (lane == 0) smax[warp] = mx;
    __syncthreads();
    if (tid == 0) {
        float mm = smax[0];
#pragma unroll
        for (int i = 1; i < 8; i++) mm = fmaxf(mm, smax[i]);
        atomicMax(&g_Cbits[h], fmap(mm));
    }
}

// ---------------- fused flash-style attention (split-m): partials = W @ h, rowsum ----------------
// Warp-M=32, 128-thread CTAs. Adjacency words loaded on demand per kc-pair (not preloaded)
// to cut live registers and restore the 4th co-resident CTA.
struct AttnSmem {
    __half hTs[2][64 * 136];    // double-buffered h tiles (cp.async), hT[o][m]  34816 B
    __half Ppk[2048], Qpk[2048];// CTA's m-range of P/Q, permuted                 8192 B
    uint2  lut[16 * 32];        // 4-bit mask index -> (m01, m89)                 4096 B
};

#define CP_ASYNC16(dst_smem, src) \
    asm volatile("cp.async.cg.shared.global [%0], [%1], 16;" :: "r"(dst_smem), "l"(src))
#define CP_COMMIT() asm volatile("cp.async.commit_group;")
#define CP_WAIT0()  asm volatile("cp.async.wait_group 0;")

#define MMA16816(acc, a0, a1, a2, a3, b0, b1) \
    asm volatile( \
        "mma.sync.aligned.m16n8k16.row.col.f32.f16.f16.f32 " \
        "{%0,%1,%2,%3}, {%4,%5,%6,%7}, {%8,%9}, {%0,%1,%2,%3};\n" \
        : "+f"((acc)[0]), "+f"((acc)[1]), "+f"((acc)[2]), "+f"((acc)[3]) \
        : "r"(a0), "r"(a1), "r"(a2), "r"(a3), "r"(b0), "r"(b1))

template<int SPLIT>
__global__ void __launch_bounds__(128, 4) k_attn(
    const __half* __restrict__ h16T,
    const float* __restrict__ elg, const float* __restrict__ erg,
    const unsigned* __restrict__ maskw,
    float* __restrict__ part, int H) {
    extern __shared__ char smem_raw[];
    AttnSmem& S = *reinterpret_cast<AttnSmem*>(smem_raw);

    constexpr int NTILES = (N_NODES / 128) / SPLIT;
    const int head = blockIdx.y;
    const int n0   = blockIdx.x * 128;
    const int tid  = threadIdx.x;
    const int lane = tid & 31, warp = tid >> 5;
    const int tig  = lane & 3, gid = lane >> 2;
    const int t2   = tig * 2;
    const int rA   = warp * 32 + gid;          // 4 rows per lane: rA, +8, +16, +24
    const int hb   = head * N_NODES;
    const int jbase = blockIdx.z * NTILES;
    const int mbase = jbase * 128;

    const float c = funmap(g_Cbits[head]);

    // stage P/Q (permuted within 16-groups: [0,1,8,9, 2,3,10,11, 4,5,12,13, 6,7,14,15])
    {
        constexpr int NM = NTILES * 128;
#pragma unroll
        for (int i = tid; i < NM; i += 128) {
            const float e_r = erg[hb + mbase + i];
            const int grp = i >> 4, ii = i & 15;
            const int pos = (ii < 8) ? ((ii >> 1) * 4 + (ii & 1))
                                     : (((ii - 8) >> 1) * 4 + 2 + (ii & 1));
            const int d = (grp << 4) + pos;
            S.Ppk[d] = __float2half_rn(expf(e_r - c));
            S.Qpk[d] = __float2half_rn(expf(0.2f * (e_r - c)));
        }
        // mask LUT: idx bits {0,1} -> m01 halves, bits {2,3} -> m89 halves
#pragma unroll
        for (int i = tid; i < 512; i += 128) {
            const int idx = i >> 5;
            unsigned m01 = ((idx & 1) ? 0x0000FFFFu : 0u) | ((idx & 2) ? 0xFFFF0000u : 0u);
            unsigned m89 = ((idx & 4) ? 0x0000FFFFu : 0u) | ((idx & 8) ? 0xFFFF0000u : 0u);
            S.lut[i] = make_uint2(m01, m89);
        }
    }
    // per-row gates (4 rows)
    __half2 g1[4], g2[4];
#pragma unroll
    for (int g = 0; g < 4; g++) {
        const float z = elg[hb + n0 + rA + 8 * g] + c;
        g1[g] = __float2half2_rn(z > 0.f ? 1.f : expf(0.8f * z));
        g2[g] = __float2half2_rn(z > 0.f ? expf(-0.8f * z) : 1.f);
    }

    float acc[2][8][4];
#pragma unroll
    for (int g = 0; g < 2; g++)
#pragma unroll
        for (int i = 0; i < 8; i++)
#pragma unroll
            for (int j = 0; j < 4; j++) acc[g][i][j] = 0.f;
    float acc_rs[2][4];
#pragma unroll
    for (int g = 0; g < 2; g++)
#pragma unroll
        for (int j = 0; j < 4; j++) acc_rs[g][j] = 0.f;

    const __half* hT = h16T + (size_t)head * 64 * N_NODES;
    const unsigned* mw = maskw + (size_t)(n0 + rA) * 128;   // row rA; rows rA+8g at +1024*g

    auto load_tile = [&](int j, int buf) {
        const int m0 = j * 128;
#pragma unroll
        for (int i = 0; i < 8; i++) {
            int idx = tid + i * 128;
            int r = idx >> 4, cc = idx & 15;
            unsigned dst = smem_u32(&S.hTs[buf][r * 136 + cc * 8]);
            CP_ASYNC16(dst, hT + (size_t)r * N_NODES + m0 + cc * 8);
        }
        CP_COMMIT();
    };

    load_tile(jbase, 0);

#pragma unroll 1
    for (int t = 0; t < NTILES; t++) {
        const int m0 = (jbase + t) * 128;
        const int ml = m0 - mbase;
        const int buf = t & 1;

        CP_WAIT0();
        __syncthreads();
        if (t + 1 < NTILES) load_tile(jbase + t + 1, buf ^ 1);

        const unsigned bone = 0x3C003C00u;
        unsigned wcur[4];
#pragma unroll
        for (int kc = 0; kc < 8; kc++) {
            // on-demand adjacency words (one 32-bit word per row per kc-pair)
            if ((kc & 1) == 0) {
#pragma unroll
                for (int g = 0; g < 4; g++)
                    wcur[g] = __ldg(mw + g * 1024 + (m0 >> 5) + (kc >> 1));
            }
            const int stot = t2 + ((kc & 1) << 4);
            // masks for 4 rows via 4-bit LUT
            uint2 mk[4];
#pragma unroll
            for (int g = 0; g < 4; g++) {
                const unsigned w = wcur[g] >> stot;
                const unsigned ix = (w & 3u) | ((w >> 6) & 12u);
                mk[g] = S.lut[(ix << 5) | lane];
            }
            // one LDS.64 each: both half2 fragments of P and Q
            const int eoff = ml + kc * 16 + 4 * tig;
            const uint2 pv = *reinterpret_cast<const uint2*>(S.Ppk + eoff);
            const uint2 qv = *reinterpret_cast<const uint2*>(S.Qpk + eoff);

            unsigned fr[2][4];
#pragma unroll
            for (int g = 0; g < 2; g++) {
                fr[g][0] = h2u(__hmax2(__hmul2(g1[2*g],   u2h(pv.x)), __hmul2(g2[2*g],   u2h(qv.x)))) & mk[2*g].x;
                fr[g][1] = h2u(__hmax2(__hmul2(g1[2*g+1], u2h(pv.x)), __hmul2(g2[2*g+1], u2h(qv.x)))) & mk[2*g+1].x;
                fr[g][2] = h2u(__hmax2(__hmul2(g1[2*g],   u2h(pv.y)), __hmul2(g2[2*g],   u2h(qv.y)))) & mk[2*g].y;
                fr[g][3] = h2u(__hmax2(__hmul2(g1[2*g+1], u2h(pv.y)), __hmul2(g2[2*g+1], u2h(qv.y)))) & mk[2*g+1].y;
                MMA16816(acc_rs[g], fr[g][0], fr[g][1], fr[g][2], fr[g][3], bone, bone);
            }
#pragma unroll
            for (int ncp = 0; ncp < 4; ncp++) {
                int gg = lane >> 3, r = lane & 7;
                int brw  = ncp * 16 + (gg >> 1) * 8 + r;
                int bcol = kc * 16 + (gg & 1) * 8;
                unsigned baddr = smem_u32(&S.hTs[buf][brw * 136 + bcol]);
                unsigned b0, b1, b2, b3;
                asm volatile("ldmatrix.sync.aligned.m8n8.x4.shared.b16 {%0,%1,%2,%3}, [%4];\n"
                             : "=r"(b0), "=r"(b1), "=r"(b2), "=r"(b3) : "r"(baddr));
#pragma unroll
                for (int g = 0; g < 2; g++) {
                    MMA16816(acc[g][2 * ncp],     fr[g][0], fr[g][1], fr[g][2], fr[g][3], b0, b1);
                    MMA16816(acc[g][2 * ncp + 1], fr[g][0], fr[g][1], fr[g][2], fr[g][3], b2, b3);
                }
            }
        }
    }

    // ---- write partials (numerator + rowsum) for 4 rows ----
    float* pbase = part + (((size_t)blockIdx.z * H + head) * N_NODES + n0) * 68;
#pragma unroll
    for (int g = 0; g < 2; g++) {
        const int r0 = rA + 16 * g, r1 = r0 + 8;
#pragma unroll
        for (int nc = 0; nc < 8; nc++) {
            int col = nc * 8 + t2;
            *reinterpret_cast<float2*>(pbase + (size_t)r0 * 68 + col) = make_float2(acc[g][nc][0], acc[g][nc][1]);
            *reinterpret_cast<float2*>(pbase + (size_t)r1 * 68 + col) = make_float2(acc[g][nc][2], acc[g][nc][3]);
        }
        if (tig == 0) {
            pbase[(size_t)r0 * 68 + 64] = acc_rs[g][0];
            pbase[(size_t)r1 * 68 + 64] = acc_rs[g][2];
        }
    }
}

// ---------------- combine split-m partials: divide + optional ELU; fp16 or fp32 out ----------------
// Also resets g_Cbits for the NEXT layer's feature kernel.
template<bool HALF_OUT>
__global__ void k_combine(const float* __restrict__ part, float* __restrict__ fout,
                          __half* __restrict__ hout,
                          int H, int SPLIT, int outStride, int applyElu) {
    if (blockIdx.x == 0 && threadIdx.x < MAXH) g_Cbits[threadIdx.x] = 0u;
    const int idx = blockIdx.x * 256 + threadIdx.x;    // over H*N*64
    const int o = idx & 63, n = (idx >> 6) & (N_NODES - 1), head = idx >> 18;
    float s = 0.f, r = 0.f;
    for (int z = 0; z < SPLIT; z++) {
        const float* pb = part + (((size_t)z * H + head) * N_NODES + n) * 68;
        s += pb[o];
        r += pb[64];
    }
    float v = s / r;
    if (applyElu) v = v > 0.f ? v : expm1f(v);
    if (HALF_OUT) hout[(size_t)n * outStride + head * 64 + o] = __float2half_rn(v);
    else          fout[(size_t)n * outStride + head * 64 + o] = v;
}

// ---------------- host orchestration ----------------
struct Scratch {
    unsigned* maskw; __half* h16T;
    float *el, *er, *part;
    __half *x16, *bufA, *bufB;
};

static void run_layer(const __half* in16, int K, const float* W, const float* a, int H,
                      float* foutp, __half* houtp, int outStride, int applyElu,
                      const Scratch& s) {
    if (K == 128) k_feat_tc<128><<<dim3(N_NODES / 128, H), 256>>>(in16, W, a, s.h16T, s.el, s.er);
    else          k_feat_tc<256><<<dim3(N_NODES / 128, H), 256>>>(in16, W, a, s.h16T, s.el, s.er);
    if (H == 4) {
        k_attn<4><<<dim3(N_NODES / 128, H, 4), 128, sizeof(AttnSmem)>>>(
            s.h16T, s.el, s.er, s.maskw, s.part, H);
        if (houtp) k_combine<true ><<<H * N_NODES * 64 / 256, 256>>>(s.part, foutp, houtp, H, 4, outStride, applyElu);
        else       k_combine<false><<<H * N_NODES * 64 / 256, 256>>>(s.part, foutp, houtp, H, 4, outStride, applyElu);
    } else {
        k_attn<8><<<dim3(N_NODES / 128, H, 8), 128, sizeof(AttnSmem)>>>(
            s.h16T, s.el, s.er, s.maskw, s.part, H);
        if (houtp) k_combine<true ><<<H * N_NODES * 64 / 256, 256>>>(s.part, foutp, houtp, H, 8, outStride, applyElu);
        else       k_combine<false><<<H * N_NODES * 64 / 256, 256>>>(s.part, foutp, houtp, H, 8, outStride, applyElu);
    }
}

extern "C" void kernel_launch(void* const* d_in, const int* in_sizes, int n_in,
                              void* d_out, int out_size) {
    (void)in_sizes; (void)n_in; (void)out_size;
    const float* x  = (const float*)d_in[0];
    const int*   adj = (const int*)d_in[1];
    const float* W0 = (const float*)d_in[2];
    const float* a0 = (const float*)d_in[3];
    const float* W1 = (const float*)d_in[4];
    const float* a1 = (const float*)d_in[5];
    const float* W2 = (const float*)d_in[6];
    const float* a2 = (const float*)d_in[7];

    cudaFuncSetAttribute(k_attn<4>, cudaFuncAttributeMaxDynamicSharedMemorySize,
                         (int)sizeof(AttnSmem));
    cudaFuncSetAttribute(k_attn<8>, cudaFuncAttributeMaxDynamicSharedMemorySize,
                         (int)sizeof(AttnSmem));

    Scratch s;
    void* p;
    cudaGetSymbolAddress(&p, g_maskw); s.maskw = (unsigned*)p;
    cudaGetSymbolAddress(&p, g_h16T);  s.h16T  = (__half*)p;
    cudaGetSymbolAddress(&p, g_el);    s.el    = (float*)p;
    cudaGetSymbolAddress(&p, g_er);    s.er    = (float*)p;
    cudaGetSymbolAddress(&p, g_part);  s.part  = (float*)p;
    cudaGetSymbolAddress(&p, g_x16);   s.x16   = (__half*)p;
    cudaGetSymbolAddress(&p, g_bufA);  s.bufA  = (__half*)p;
    cudaGetSymbolAddress(&p, g_bufB);  s.bufB  = (__half*)p;

    k_mask<<<N_NODES, 1024>>>(adj, s.maskw);
    k_x2h<<<(N_NODES * 128 / 4 + 255) / 256, 256>>>(x, s.x16, N_NODES * 128 / 4);

    run_layer(s.x16,  128, W0, a0, 4, nullptr,        s.bufA, 256, 1, s);
    run_layer(s.bufA, 256, W1, a1, 4, nullptr,        s.bufB, 256, 1, s);
    run_layer(s.bufB, 256, W2, a2, 1, (float*)d_out,  nullptr, 64, 0, s);
}